// round 1
// baseline (speedup 1.0000x reference)
#include <cuda_runtime.h>
#include <cuda_bf16.h>
#include <cstdint>

#define Nn 50000
#define Ee 800000
#define Rr 8
#define Hh 128
#define Bb 10

// ---------------- device scratch (allocation-free rule: __device__ globals) ---
__device__ float g_xW[(size_t)Rr * Nn * Hh];   // per-relation transformed feats
__device__ float g_h [(size_t)Nn * Hh];        // inter-layer node feats
__device__ float g_si[(size_t)Rr * Nn];        // target-side score per (r,n)
__device__ float g_sj[(size_t)Rr * Nn];        // source-side score per (r,n)
__device__ int   g_deg[Nn];
__device__ int   g_off[Nn + 1];
__device__ int   g_cur[Nn];
__device__ int   g_eid[Ee];

// ---------------- CSR build --------------------------------------------------
__global__ void k_zero_deg() {
    int i = blockIdx.x * blockDim.x + threadIdx.x;
    if (i < Nn) g_deg[i] = 0;
}

__global__ void k_hist(const int* __restrict__ tgt) {
    int e = blockIdx.x * blockDim.x + threadIdx.x;
    if (e < Ee) atomicAdd(&g_deg[tgt[e]], 1);
}

// single-block scan over N (49 chunks of 1024)
__global__ void k_scan() {
    __shared__ int sh[1024];
    __shared__ int carry;
    int tid = threadIdx.x;
    if (tid == 0) { carry = 0; g_off[0] = 0; }
    __syncthreads();
    for (int base = 0; base < Nn; base += 1024) {
        int i = base + tid;
        int v = (i < Nn) ? g_deg[i] : 0;
        sh[tid] = v;
        __syncthreads();
        #pragma unroll
        for (int s = 1; s < 1024; s <<= 1) {
            int t = (tid >= s) ? sh[tid - s] : 0;
            __syncthreads();
            sh[tid] += t;
            __syncthreads();
        }
        int inc = sh[tid] + carry;
        if (i < Nn) { g_off[i + 1] = inc; g_cur[i] = inc - v; }
        __syncthreads();
        if (tid == 1023) carry = inc;
        __syncthreads();
    }
}

__global__ void k_scatter(const int* __restrict__ tgt) {
    int e = blockIdx.x * blockDim.x + threadIdx.x;
    if (e < Ee) {
        int pos = atomicAdd(&g_cur[tgt[e]], 1);
        g_eid[pos] = e;
    }
}

// ---------------- register-blocked SGEMM: C[n,h] = sum_k A[n,k]*B[k,h] -------
// 128x128 tile, K=128 in 16-chunks, 256 threads, 8x8 per thread.
// blockIdx.y selects relation (B += y*128*128, C += y*nrows*128).
template <bool TRANSB, bool BIAS, bool RELU>
__global__ void k_gemm128(const float* __restrict__ A, const float* __restrict__ Bmat,
                          const float* __restrict__ bias, float* __restrict__ Cbase,
                          int nrows) {
    const float* B = Bmat + (size_t)blockIdx.y * Hh * Hh;
    float* C = Cbase + (size_t)blockIdx.y * (size_t)nrows * Hh;
    __shared__ float As[16][132];
    __shared__ float Bs[16][132];
    int t  = threadIdx.x;
    int tx = t & 15, ty = t >> 4;
    int rowBase = blockIdx.x * 128;

    float acc[8][8];
    #pragma unroll
    for (int m = 0; m < 8; m++)
        #pragma unroll
        for (int n = 0; n < 8; n++) acc[m][n] = 0.f;

    for (int kk = 0; kk < 128; kk += 16) {
        // A chunk: 128 rows x 16 k, stored transposed As[k][row]
        #pragma unroll
        for (int i = 0; i < 2; i++) {
            int lin = t + i * 256;        // 0..511 float4 loads
            int row = lin >> 2;           // 0..127
            int c4  = (lin & 3) * 4;      // 0,4,8,12
            float4 v = make_float4(0.f, 0.f, 0.f, 0.f);
            if (rowBase + row < nrows)
                v = *(const float4*)&A[(size_t)(rowBase + row) * 128 + kk + c4];
            As[c4 + 0][row] = v.x; As[c4 + 1][row] = v.y;
            As[c4 + 2][row] = v.z; As[c4 + 3][row] = v.w;
        }
        // B chunk: 16 k x 128 cols
        if (!TRANSB) {
            #pragma unroll
            for (int i = 0; i < 2; i++) {
                int lin = t + i * 256;
                int r  = lin >> 5;          // 0..15
                int c4 = (lin & 31) * 4;    // 0..124
                float4 v = *(const float4*)&B[(size_t)(kk + r) * 128 + c4];
                *(float4*)&Bs[r][c4] = v;
            }
        } else {
            #pragma unroll
            for (int i = 0; i < 8; i++) {
                int lin = t + i * 256;      // 2048 elems
                int r = lin >> 7;           // 0..15
                int c = lin & 127;
                Bs[r][c] = B[(size_t)c * 128 + kk + r];
            }
        }
        __syncthreads();
        #pragma unroll
        for (int k = 0; k < 16; k++) {
            float4 a0 = *(const float4*)&As[k][ty * 8];
            float4 a1 = *(const float4*)&As[k][ty * 8 + 4];
            float4 b0 = *(const float4*)&Bs[k][tx * 8];
            float4 b1 = *(const float4*)&Bs[k][tx * 8 + 4];
            float a[8] = {a0.x, a0.y, a0.z, a0.w, a1.x, a1.y, a1.z, a1.w};
            float b[8] = {b0.x, b0.y, b0.z, b0.w, b1.x, b1.y, b1.z, b1.w};
            #pragma unroll
            for (int m = 0; m < 8; m++)
                #pragma unroll
                for (int n = 0; n < 8; n++) acc[m][n] = fmaf(a[m], b[n], acc[m][n]);
        }
        __syncthreads();
    }
    #pragma unroll
    for (int m = 0; m < 8; m++) {
        int row = rowBase + ty * 8 + m;
        if (row >= nrows) continue;
        #pragma unroll
        for (int n4 = 0; n4 < 2; n4++) {
            int col = tx * 8 + n4 * 4;
            float4 v = make_float4(acc[m][n4 * 4 + 0], acc[m][n4 * 4 + 1],
                                   acc[m][n4 * 4 + 2], acc[m][n4 * 4 + 3]);
            if (BIAS) {
                float4 bv = *(const float4*)&bias[col];
                v.x += bv.x; v.y += bv.y; v.z += bv.z; v.w += bv.w;
            }
            if (RELU) {
                v.x = fmaxf(v.x, 0.f); v.y = fmaxf(v.y, 0.f);
                v.z = fmaxf(v.z, 0.f); v.w = fmaxf(v.w, 0.f);
            }
            *(float4*)&C[(size_t)row * 128 + col] = v;
        }
    }
}

// ---------------- per-(r,n) attention scores ---------------------------------
__global__ void k_scores(const float* __restrict__ q, const float* __restrict__ kvec) {
    int wid  = (blockIdx.x * blockDim.x + threadIdx.x) >> 5;
    int lane = threadIdx.x & 31;
    if (wid >= Rr * Nn) return;
    float4 xv = *(const float4*)&g_xW[(size_t)wid * 128 + lane * 4];
    float4 qv = *(const float4*)&q[lane * 4];
    float4 kv = *(const float4*)&kvec[lane * 4];
    float sq = xv.x * qv.x + xv.y * qv.y + xv.z * qv.z + xv.w * qv.w;
    float sk = xv.x * kv.x + xv.y * kv.y + xv.z * kv.z + xv.w * kv.w;
    #pragma unroll
    for (int s = 16; s; s >>= 1) {
        sq += __shfl_xor_sync(0xffffffffu, sq, s);
        sk += __shfl_xor_sync(0xffffffffu, sk, s);
    }
    if (lane == 0) { g_si[wid] = sq; g_sj[wid] = sk; }
}

// ---------------- softmax + aggregation: one warp per target node ------------
__global__ void k_agg(const int* __restrict__ srcA, const int* __restrict__ et,
                      const float* __restrict__ bias, float* __restrict__ out,
                      int relu) {
    int wid  = (blockIdx.x * blockDim.x + threadIdx.x) >> 5;
    int lane = threadIdx.x & 31;
    if (wid >= Nn) return;
    int n  = wid;
    int o0 = g_off[n], o1 = g_off[n + 1];

    // pass 1: max alpha (warp-parallel over edges)
    float amax = -1e30f;
    for (int i = o0 + lane; i < o1; i += 32) {
        int e = g_eid[i];
        int r = et[e];
        int s = srcA[e];
        float al = g_si[(size_t)r * Nn + n] + g_sj[(size_t)r * Nn + s];
        al = al > 0.f ? al : 0.2f * al;
        amax = fmaxf(amax, al);
    }
    #pragma unroll
    for (int s = 16; s; s >>= 1) amax = fmaxf(amax, __shfl_xor_sync(0xffffffffu, amax, s));

    // pass 2: exp-sum + weighted feature gather (lanes split the H dim)
    float den = 0.f;
    float4 acc = make_float4(0.f, 0.f, 0.f, 0.f);
    int h0 = lane * 4;
    for (int i = o0; i < o1; i++) {
        int e = g_eid[i];
        int r = et[e];
        int s = srcA[e];
        float al = g_si[(size_t)r * Nn + n] + g_sj[(size_t)r * Nn + s];
        al = al > 0.f ? al : 0.2f * al;
        float p = __expf(al - amax);
        den += p;
        const float4 v = *(const float4*)&g_xW[((size_t)r * Nn + s) * 128 + h0];
        acc.x = fmaf(p, v.x, acc.x);
        acc.y = fmaf(p, v.y, acc.y);
        acc.z = fmaf(p, v.z, acc.z);
        acc.w = fmaf(p, v.w, acc.w);
    }
    float sc = 1.f / (den + 1e-16f);
    float4 b4 = *(const float4*)&bias[h0];
    float4 o;
    o.x = acc.x * sc + b4.x;
    o.y = acc.y * sc + b4.y;
    o.z = acc.z * sc + b4.z;
    o.w = acc.w * sc + b4.w;
    if (relu) {
        o.x = fmaxf(o.x, 0.f); o.y = fmaxf(o.y, 0.f);
        o.z = fmaxf(o.z, 0.f); o.w = fmaxf(o.w, 0.f);
    }
    *(float4*)&out[(size_t)n * 128 + h0] = o;
}

// ---------------- host orchestration -----------------------------------------
extern "C" void kernel_launch(void* const* d_in, const int* in_sizes, int n_in,
                              void* d_out, int out_size) {
    const float* x   = (const float*)d_in[0];
    const int*   ei  = (const int*)d_in[1];
    const int*   src = ei;
    const int*   tgt = ei + Ee;
    const int*   et  = (const int*)d_in[2];
    const float* W1  = (const float*)d_in[4];
    const float* q1  = (const float*)d_in[5];
    const float* k1  = (const float*)d_in[6];
    const float* b1  = (const float*)d_in[7];
    const float* W2  = (const float*)d_in[8];
    const float* q2  = (const float*)d_in[9];
    const float* k2  = (const float*)d_in[10];
    const float* b2  = (const float*)d_in[11];
    const float* Wl  = (const float*)d_in[12];
    const float* bl  = (const float*)d_in[13];
    float* out = (float*)d_out;

    void* p_xW = nullptr; void* p_h = nullptr;
    cudaGetSymbolAddress(&p_xW, g_xW);
    cudaGetSymbolAddress(&p_h, g_h);
    float* xW = (float*)p_xW;
    float* h  = (float*)p_h;

    const int NT = 256;
    // CSR build (shared by both layers)
    k_zero_deg<<<(Nn + NT - 1) / NT, NT>>>();
    k_hist<<<(Ee + NT - 1) / NT, NT>>>(tgt);
    k_scan<<<1, 1024>>>();
    k_scatter<<<(Ee + NT - 1) / NT, NT>>>(tgt);

    dim3 gemmGridRel((Nn + 127) / 128, Rr);
    dim3 gemmGridLin((Nn + 127) / 128, 1);
    int scoreBlocks = (Rr * Nn * 32 + NT - 1) / NT;  // 1 warp per (r,n)
    int aggBlocks   = (Nn * 32 + NT - 1) / NT;       // 1 warp per node

    // layer 1
    k_gemm128<false, false, false><<<gemmGridRel, NT>>>(x, W1, nullptr, xW, Nn);
    k_scores<<<scoreBlocks, NT>>>(q1, k1);
    k_agg<<<aggBlocks, NT>>>(src, et, b1, h, 1);

    // layer 2
    k_gemm128<false, false, false><<<gemmGridRel, NT>>>(h, W2, nullptr, xW, Nn);
    k_scores<<<scoreBlocks, NT>>>(q2, k2);
    k_agg<<<aggBlocks, NT>>>(src, et, b2, h, 1);

    // final linear: out = h @ Wl^T + bl
    k_gemm128<true, true, false><<<gemmGridLin, NT>>>(h, Wl, bl, out, Nn);
}

// round 8
// speedup vs baseline: 1.4706x; 1.4706x over previous
#include <cuda_runtime.h>
#include <cuda_bf16.h>
#include <cstdint>

#define Nn 50000
#define Ee 800000
#define Rr 8
#define Hh 128
#define Bb 10

// ---------------- device scratch ---------------------------------------------
__device__ float g_xW[(size_t)Rr * Nn * Hh];   // per-relation transformed feats (fp32)
__device__ float g_si[(size_t)Rr * Nn];        // target-side score per (r,n)
__device__ float g_sj[(size_t)Rr * Nn];        // source-side score per (r,n)
__device__ __nv_bfloat16 g_Ahi[(size_t)Nn * Hh];  // current layer input, hi split
__device__ __nv_bfloat16 g_Alo[(size_t)Nn * Hh];  // current layer input, lo split
__device__ __nv_bfloat16 g_W1hi[(size_t)Rr * Hh * Hh]; // W1^T [r][h][k] splits
__device__ __nv_bfloat16 g_W1lo[(size_t)Rr * Hh * Hh];
__device__ __nv_bfloat16 g_W2hi[(size_t)Rr * Hh * Hh];
__device__ __nv_bfloat16 g_W2lo[(size_t)Rr * Hh * Hh];
__device__ __nv_bfloat16 g_Wlhi[(size_t)Hh * Hh];      // Wl [o][k] splits (no transpose)
__device__ __nv_bfloat16 g_Wllo[(size_t)Hh * Hh];
__device__ int   g_deg[Nn];
__device__ int   g_off[Nn + 1];
__device__ int   g_cur[Nn];
__device__ int   g_eid[Ee];

// ---------------- portable tensor-core PTX helpers ----------------------------
__device__ __forceinline__ uint32_t smem_to_u32(const void* p) {
    uint32_t a;
    asm("{ .reg .u64 t; cvta.to.shared.u64 t, %1; cvt.u32.u64 %0, t; }" : "=r"(a) : "l"(p));
    return a;
}
__device__ __forceinline__ void ldm_x4(uint32_t& r0, uint32_t& r1, uint32_t& r2, uint32_t& r3,
                                       uint32_t addr) {
    asm volatile("ldmatrix.sync.aligned.m8n8.x4.shared.b16 {%0,%1,%2,%3}, [%4];"
                 : "=r"(r0), "=r"(r1), "=r"(r2), "=r"(r3) : "r"(addr));
}
__device__ __forceinline__ void mma16816(float* d, const uint32_t* a, const uint32_t* b) {
    asm volatile("mma.sync.aligned.m16n8k16.row.col.f32.bf16.bf16.f32 "
                 "{%0,%1,%2,%3}, {%4,%5,%6,%7}, {%8,%9}, {%0,%1,%2,%3};"
                 : "+f"(d[0]), "+f"(d[1]), "+f"(d[2]), "+f"(d[3])
                 : "r"(a[0]), "r"(a[1]), "r"(a[2]), "r"(a[3]), "r"(b[0]), "r"(b[1]));
}

// ---------------- CSR build --------------------------------------------------
__global__ void k_zero_deg() {
    int i = blockIdx.x * blockDim.x + threadIdx.x;
    if (i < Nn) g_deg[i] = 0;
}
__global__ void k_hist(const int* __restrict__ tgt) {
    int e = blockIdx.x * blockDim.x + threadIdx.x;
    if (e < Ee) atomicAdd(&g_deg[tgt[e]], 1);
}
__global__ void k_scan() {
    __shared__ int sh[1024];
    __shared__ int carry;
    int tid = threadIdx.x;
    if (tid == 0) { carry = 0; g_off[0] = 0; }
    __syncthreads();
    for (int base = 0; base < Nn; base += 1024) {
        int i = base + tid;
        int v = (i < Nn) ? g_deg[i] : 0;
        sh[tid] = v;
        __syncthreads();
        #pragma unroll
        for (int s = 1; s < 1024; s <<= 1) {
            int t = (tid >= s) ? sh[tid - s] : 0;
            __syncthreads();
            sh[tid] += t;
            __syncthreads();
        }
        int inc = sh[tid] + carry;
        if (i < Nn) { g_off[i + 1] = inc; g_cur[i] = inc - v; }
        __syncthreads();
        if (tid == 1023) carry = inc;
        __syncthreads();
    }
}
__global__ void k_scatter(const int* __restrict__ tgt) {
    int e = blockIdx.x * blockDim.x + threadIdx.x;
    if (e < Ee) {
        int pos = atomicAdd(&g_cur[tgt[e]], 1);
        g_eid[pos] = e;
    }
}

// ---------------- bf16 hi/lo split prep --------------------------------------
__device__ __forceinline__ void split2(float v, __nv_bfloat16& hi, __nv_bfloat16& lo) {
    hi = __float2bfloat16(v);
    lo = __float2bfloat16(v - __bfloat162float(hi));
}
__global__ void k_split_x(const float* __restrict__ x) {
    int i = blockIdx.x * blockDim.x + threadIdx.x;
    if (i >= Nn * Hh) return;
    __nv_bfloat16 h, l;
    split2(x[i], h, l);
    g_Ahi[i] = h; g_Alo[i] = l;
}
// W: [R][K=128][H=128] -> out[r][h][k] (transposed per relation)
__global__ void k_prep_wrel(const float* __restrict__ W, __nv_bfloat16* __restrict__ hi,
                            __nv_bfloat16* __restrict__ lo) {
    int i = blockIdx.x * blockDim.x + threadIdx.x;
    if (i >= Rr * Hh * Hh) return;
    int r = i >> 14, rem = i & 16383, h = rem >> 7, k = rem & 127;
    float v = W[(size_t)r * 16384 + (size_t)k * 128 + h];
    __nv_bfloat16 a, b; split2(v, a, b);
    hi[i] = a; lo[i] = b;
}
// Wl: [O=128][K=128] already B-layout
__global__ void k_prep_wl(const float* __restrict__ Wl) {
    int i = blockIdx.x * blockDim.x + threadIdx.x;
    if (i >= Hh * Hh) return;
    __nv_bfloat16 a, b; split2(Wl[i], a, b);
    g_Wlhi[i] = a; g_Wllo[i] = b;
}

// ---------------- mma.sync GEMM: C[r] = A(128,128) x W[r]^T ------------------
// bf16x3 split accuracy, fp32 register accumulators. One CTA = 128-row tile,
// loops over NREL relations reusing A in SMEM. Epilogue fuses q/k score dots.
// SMEM rows padded to 136 bf16 (272B): consecutive rows shift 4 banks ->
// ldmatrix (16B per row across 8 rows) is conflict-free.
#define LDP 136
#define SM_QK   0                         // 128 float2 (q,k) or 128 float bias
#define SM_SC   1024                      // 128 float2 cross-warp score partials
#define SM_A_HI 2048
#define SM_A_LO (SM_A_HI + 128 * LDP * 2) // 2048+34816
#define SM_W_HI (SM_A_LO + 128 * LDP * 2)
#define SM_W_LO (SM_W_HI + 128 * LDP * 2)
#define SM_TOT  (SM_W_LO + 128 * LDP * 2) // 141312

template <int NREL, bool SCORES, bool BIAS>
__global__ __launch_bounds__(256, 1) void k_mmagemm(
    const __nv_bfloat16* __restrict__ Ahi, const __nv_bfloat16* __restrict__ Alo,
    const __nv_bfloat16* __restrict__ Whi, const __nv_bfloat16* __restrict__ Wlo,
    const float* __restrict__ qv, const float* __restrict__ kv,
    const float* __restrict__ bias,
    float* __restrict__ Cout, float* __restrict__ si, float* __restrict__ sj) {
    extern __shared__ char smem[];
    uint32_t sb = smem_to_u32(smem);
    __nv_bfloat16* sAhi = (__nv_bfloat16*)(smem + SM_A_HI);
    __nv_bfloat16* sAlo = (__nv_bfloat16*)(smem + SM_A_LO);
    __nv_bfloat16* sWhi = (__nv_bfloat16*)(smem + SM_W_HI);
    __nv_bfloat16* sWlo = (__nv_bfloat16*)(smem + SM_W_LO);
    float2* sqk = (float2*)(smem + SM_QK);
    float*  sbv = (float*)(smem + SM_QK);
    float2* ssc = (float2*)(smem + SM_SC);

    int tid = threadIdx.x;
    int lane = tid & 31;
    int warp = tid >> 5;
    int warp_m = warp >> 1;          // 0..3 -> rows 32*warp_m
    int warp_n = warp & 1;           // 0..1 -> cols 64*warp_n
    int rowBase = blockIdx.x * 128;

    if (SCORES) {
        if (tid < 128) { float2 v; v.x = qv[tid]; v.y = kv[tid]; sqk[tid] = v; }
    } else if (BIAS) {
        if (tid < 128) sbv[tid] = bias[tid];
    }

    // stage A tile (hi+lo), row-major padded
    for (int i = tid; i < 2048; i += 256) {
        int row = i >> 4;
        int k8  = (i & 15) << 3;
        int node = rowBase + row;
        float4 vh = make_float4(0.f, 0.f, 0.f, 0.f);
        float4 vl = make_float4(0.f, 0.f, 0.f, 0.f);
        if (node < Nn) {
            vh = *(const float4*)&Ahi[(size_t)node * 128 + k8];
            vl = *(const float4*)&Alo[(size_t)node * 128 + k8];
        }
        *(float4*)&sAhi[row * LDP + k8] = vh;
        *(float4*)&sAlo[row * LDP + k8] = vl;
    }

    // ldmatrix per-lane address components
    int lr = lane & 7;
    int aRowOff = lr + ((lane >> 3) & 1) * 8;     // m0/m1 rows, m2/m3 rows
    int aKOff   = (lane >> 4) * 8;                 // k halves
    int bRowOff = lr + ((lane >= 16) ? 8 : 0);
    int bKOff   = ((lane >> 3) & 1) * 8;
    int qrow = lane >> 2;
    int qc   = (lane & 3) * 2;

    for (int r = 0; r < NREL; r++) {
        // stage W tile for relation r (all CTAs read same W -> L2 hits)
        const __nv_bfloat16* wh = Whi + (size_t)r * 16384;
        const __nv_bfloat16* wl = Wlo + (size_t)r * 16384;
        for (int i = tid; i < 2048; i += 256) {
            int row = i >> 4;
            int k8  = (i & 15) << 3;
            *(float4*)&sWhi[row * LDP + k8] = *(const float4*)&wh[(size_t)row * 128 + k8];
            *(float4*)&sWlo[row * LDP + k8] = *(const float4*)&wl[(size_t)row * 128 + k8];
        }
        __syncthreads();

        float acc[2][8][4];
        #pragma unroll
        for (int mt = 0; mt < 2; mt++)
            #pragma unroll
            for (int nt = 0; nt < 8; nt++)
                #pragma unroll
                for (int j = 0; j < 4; j++) acc[mt][nt][j] = 0.f;

        // three passes: Ahi*Whi + Ahi*Wlo + Alo*Whi (fp32 accumulate)
        #pragma unroll
        for (int pass = 0; pass < 3; pass++) {
            uint32_t aBase = sb + ((pass == 2) ? SM_A_LO : SM_A_HI);
            uint32_t wBase = sb + ((pass == 1) ? SM_W_LO : SM_W_HI);
            #pragma unroll
            for (int k16 = 0; k16 < 128; k16 += 16) {
                uint32_t a[2][4];
                #pragma unroll
                for (int mt = 0; mt < 2; mt++) {
                    uint32_t idx = (uint32_t)((warp_m * 32 + mt * 16 + aRowOff) * LDP + k16 + aKOff);
                    ldm_x4(a[mt][0], a[mt][1], a[mt][2], a[mt][3], aBase + idx * 2);
                }
                uint32_t b[8][2];
                #pragma unroll
                for (int nt2 = 0; nt2 < 4; nt2++) {
                    uint32_t idx = (uint32_t)((warp_n * 64 + nt2 * 16 + bRowOff) * LDP + k16 + bKOff);
                    ldm_x4(b[2 * nt2][0], b[2 * nt2][1], b[2 * nt2 + 1][0], b[2 * nt2 + 1][1],
                           wBase + idx * 2);
                }
                #pragma unroll
                for (int mt = 0; mt < 2; mt++)
                    #pragma unroll
                    for (int nt = 0; nt < 8; nt++) mma16816(acc[mt][nt], a[mt], b[nt]);
            }
        }

        // epilogue: write C, fused score partial dots
        float psq[2][2], psk[2][2];
        #pragma unroll
        for (int mt = 0; mt < 2; mt++) {
            #pragma unroll
            for (int half = 0; half < 2; half++) {
                int row  = warp_m * 32 + mt * 16 + half * 8 + qrow;
                int node = rowBase + row;
                bool valid = node < Nn;
                float* dst = SCORES ? &Cout[((size_t)r * Nn + node) * 128]
                                    : &Cout[(size_t)node * 128];
                float sq = 0.f, sk = 0.f;
                #pragma unroll
                for (int nt = 0; nt < 8; nt++) {
                    int col = warp_n * 64 + nt * 8 + qc;
                    float v0 = acc[mt][nt][half * 2];
                    float v1 = acc[mt][nt][half * 2 + 1];
                    if (BIAS) { v0 += sbv[col]; v1 += sbv[col + 1]; }
                    if (valid) { float2 o; o.x = v0; o.y = v1; *(float2*)&dst[col] = o; }
                    if (SCORES) {
                        float2 q0 = sqk[col], q1 = sqk[col + 1];
                        sq = fmaf(v0, q0.x, fmaf(v1, q1.x, sq));
                        sk = fmaf(v0, q0.y, fmaf(v1, q1.y, sk));
                    }
                }
                if (SCORES) {
                    sq += __shfl_xor_sync(0xffffffffu, sq, 1);
                    sq += __shfl_xor_sync(0xffffffffu, sq, 2);
                    sk += __shfl_xor_sync(0xffffffffu, sk, 1);
                    sk += __shfl_xor_sync(0xffffffffu, sk, 2);
                    psq[mt][half] = sq; psk[mt][half] = sk;
                }
            }
        }
        if (SCORES) {
            if (warp_n == 0 && (lane & 3) == 0) {
                #pragma unroll
                for (int mt = 0; mt < 2; mt++)
                    #pragma unroll
                    for (int half = 0; half < 2; half++) {
                        int row = warp_m * 32 + mt * 16 + half * 8 + qrow;
                        float2 v; v.x = psq[mt][half]; v.y = psk[mt][half];
                        ssc[row] = v;
                    }
            }
            __syncthreads();
            if (warp_n == 1 && (lane & 3) == 0) {
                #pragma unroll
                for (int mt = 0; mt < 2; mt++)
                    #pragma unroll
                    for (int half = 0; half < 2; half++) {
                        int row = warp_m * 32 + mt * 16 + half * 8 + qrow;
                        int node = rowBase + row;
                        if (node < Nn) {
                            float2 o = ssc[row];
                            si[(size_t)r * Nn + node] = psq[mt][half] + o.x;
                            sj[(size_t)r * Nn + node] = psk[mt][half] + o.y;
                        }
                    }
            }
        }
        __syncthreads();  // all reads of W/A/ssc done before next relation
    }
}

// ---------------- softmax + aggregation: one warp per target node ------------
// Writes result as bf16 hi/lo splits (input for next tensor-core GEMM).
__global__ void k_agg(const int* __restrict__ srcA, const int* __restrict__ et,
                      const float* __restrict__ bias) {
    int wid = (blockIdx.x * blockDim.x + threadIdx.x) >> 5;
    int lane = threadIdx.x & 31;
    if (wid >= Nn) return;
    int n = wid;
    int o0 = g_off[n], o1 = g_off[n + 1];

    float amax = -1e30f;
    for (int i = o0 + lane; i < o1; i += 32) {
        int e = g_eid[i];
        int r = et[e];
        int s = srcA[e];
        float al = g_si[(size_t)r * Nn + n] + g_sj[(size_t)r * Nn + s];
        al = al > 0.f ? al : 0.2f * al;
        amax = fmaxf(amax, al);
    }
    #pragma unroll
    for (int s = 16; s; s >>= 1) amax = fmaxf(amax, __shfl_xor_sync(0xffffffffu, amax, s));

    float den = 0.f;
    float4 acc = make_float4(0.f, 0.f, 0.f, 0.f);
    int h0 = lane * 4;
    for (int i = o0; i < o1; i++) {
        int e = g_eid[i];
        int r = et[e];
        int s = srcA[e];
        float al = g_si[(size_t)r * Nn + n] + g_sj[(size_t)r * Nn + s];
        al = al > 0.f ? al : 0.2f * al;
        float p = __expf(al - amax);
        den += p;
        const float4 v = *(const float4*)&g_xW[((size_t)r * Nn + s) * 128 + h0];
        acc.x = fmaf(p, v.x, acc.x);
        acc.y = fmaf(p, v.y, acc.y);
        acc.z = fmaf(p, v.z, acc.z);
        acc.w = fmaf(p, v.w, acc.w);
    }
    float sc = 1.f / (den + 1e-16f);
    float4 b4 = *(const float4*)&bias[h0];
    float4 o;
    o.x = fmaxf(acc.x * sc + b4.x, 0.f);
    o.y = fmaxf(acc.y * sc + b4.y, 0.f);
    o.z = fmaxf(acc.z * sc + b4.z, 0.f);
    o.w = fmaxf(acc.w * sc + b4.w, 0.f);
    __nv_bfloat16 hx, lx, hy, ly, hz, lz, hw, lw;
    split2(o.x, hx, lx); split2(o.y, hy, ly);
    split2(o.z, hz, lz); split2(o.w, hw, lw);
    __nv_bfloat162* hp = (__nv_bfloat162*)&g_Ahi[(size_t)n * 128 + h0];
    __nv_bfloat162* lp = (__nv_bfloat162*)&g_Alo[(size_t)n * 128 + h0];
    hp[0] = __nv_bfloat162(hx, hy); hp[1] = __nv_bfloat162(hz, hw);
    lp[0] = __nv_bfloat162(lx, ly); lp[1] = __nv_bfloat162(lz, lw);
}

// ---------------- host orchestration -----------------------------------------
extern "C" void kernel_launch(void* const* d_in, const int* in_sizes, int n_in,
                              void* d_out, int out_size) {
    const float* x   = (const float*)d_in[0];
    const int*   ei  = (const int*)d_in[1];
    const int*   src = ei;
    const int*   tgt = ei + Ee;
    const int*   et  = (const int*)d_in[2];
    const float* W1  = (const float*)d_in[4];
    const float* q1  = (const float*)d_in[5];
    const float* k1  = (const float*)d_in[6];
    const float* b1  = (const float*)d_in[7];
    const float* W2  = (const float*)d_in[8];
    const float* q2  = (const float*)d_in[9];
    const float* k2  = (const float*)d_in[10];
    const float* b2  = (const float*)d_in[11];
    const float* Wl  = (const float*)d_in[12];
    const float* bl  = (const float*)d_in[13];
    float* out = (float*)d_out;

    void *p_xW, *p_si, *p_sj, *p_Ahi, *p_Alo;
    void *p_W1hi, *p_W1lo, *p_W2hi, *p_W2lo, *p_Wlhi, *p_Wllo;
    cudaGetSymbolAddress(&p_xW, g_xW);
    cudaGetSymbolAddress(&p_si, g_si);
    cudaGetSymbolAddress(&p_sj, g_sj);
    cudaGetSymbolAddress(&p_Ahi, g_Ahi);
    cudaGetSymbolAddress(&p_Alo, g_Alo);
    cudaGetSymbolAddress(&p_W1hi, g_W1hi);
    cudaGetSymbolAddress(&p_W1lo, g_W1lo);
    cudaGetSymbolAddress(&p_W2hi, g_W2hi);
    cudaGetSymbolAddress(&p_W2lo, g_W2lo);
    cudaGetSymbolAddress(&p_Wlhi, g_Wlhi);
    cudaGetSymbolAddress(&p_Wllo, g_Wllo);

    cudaFuncSetAttribute(k_mmagemm<Rr, true, false>,
                         cudaFuncAttributeMaxDynamicSharedMemorySize, SM_TOT);
    cudaFuncSetAttribute(k_mmagemm<1, false, true>,
                         cudaFuncAttributeMaxDynamicSharedMemorySize, SM_TOT);

    const int NT = 256;
    // CSR build (edge structure shared by both layers)
    k_zero_deg<<<(Nn + NT - 1) / NT, NT>>>();
    k_hist<<<(Ee + NT - 1) / NT, NT>>>(tgt);
    k_scan<<<1, 1024>>>();
    k_scatter<<<(Ee + NT - 1) / NT, NT>>>(tgt);

    // input/weight splits
    k_split_x<<<(Nn * Hh + NT - 1) / NT, NT>>>(x);
    k_prep_wrel<<<(Rr * Hh * Hh + NT - 1) / NT, NT>>>(W1, (__nv_bfloat16*)p_W1hi, (__nv_bfloat16*)p_W1lo);
    k_prep_wrel<<<(Rr * Hh * Hh + NT - 1) / NT, NT>>>(W2, (__nv_bfloat16*)p_W2hi, (__nv_bfloat16*)p_W2lo);
    k_prep_wl<<<(Hh * Hh + NT - 1) / NT, NT>>>(Wl);

    int gemmGrid = (Nn + 127) / 128;
    int aggBlocks = (Nn * 32 + NT - 1) / NT;

    // layer 1: per-relation GEMM + fused scores, then softmax-aggregate
    k_mmagemm<Rr, true, false><<<gemmGrid, NT, SM_TOT>>>(
        (const __nv_bfloat16*)p_Ahi, (const __nv_bfloat16*)p_Alo,
        (const __nv_bfloat16*)p_W1hi, (const __nv_bfloat16*)p_W1lo,
        q1, k1, nullptr, (float*)p_xW, (float*)p_si, (float*)p_sj);
    k_agg<<<aggBlocks, NT>>>(src, et, b1);

    // layer 2
    k_mmagemm<Rr, true, false><<<gemmGrid, NT, SM_TOT>>>(
        (const __nv_bfloat16*)p_Ahi, (const __nv_bfloat16*)p_Alo,
        (const __nv_bfloat16*)p_W2hi, (const __nv_bfloat16*)p_W2lo,
        q2, k2, nullptr, (float*)p_xW, (float*)p_si, (float*)p_sj);
    k_agg<<<aggBlocks, NT>>>(src, et, b2);

    // final linear: out = h @ Wl^T + bl
    k_mmagemm<1, false, true><<<gemmGrid, NT, SM_TOT>>>(
        (const __nv_bfloat16*)p_Ahi, (const __nv_bfloat16*)p_Alo,
        (const __nv_bfloat16*)p_Wlhi, (const __nv_bfloat16*)p_Wllo,
        nullptr, nullptr, bl, out, nullptr, nullptr);
}